// round 15
// baseline (speedup 1.0000x reference)
#include <cuda_runtime.h>
#include <math.h>

// ---------------------------------------------------------------------------
// VoxelBackBone8x decoder: 8 x (gather-GEMM over 27 taps + BN + relu)
// R15: == R14 gemm kernels (passed, 1244us), launch pipeline restructured:
//   * zero kernel -> 3 cudaMemsetAsync nodes (not kernel launches)
//   * scan fused into scatter (each 1024-thread scatter block re-scans its
//     layer's hist in smem) -> one launch fewer, identical perm
//   * order: hist(0) scatter_scan(1) L1(2) L2(3) -> ncu capture slot 3 = L2,
//     finally giving per-layer visibility into the ~815us sparse residual.
// ---------------------------------------------------------------------------

#define MAXROWS 102400
#define NB 1024

__device__ float g_bufA[MAXROWS * 64];
__device__ float g_bufB[MAXROWS * 64];
__device__ float g_stats[8 * 2 * 64];   // per layer: [sum(64), sumsq(64)]
__device__ int      g_perm[7][MAXROWS];
__device__ unsigned g_keys[7][MAXROWS];
__device__ unsigned g_hist[7 * NB];
__device__ unsigned g_cnt[7 * NB];

struct PermArgs {
    const int* tab[7];
    int n[7];
    int cum[8];    // cumulative 256-thread block counts (hist)
    int cum2[8];   // cumulative 1024-thread block counts (scatter_scan)
};

// ---------------------------------------------------------------------------
// Fused permutation build over all 7 layers.
// ---------------------------------------------------------------------------
__global__ void mask_hist_all_kernel(PermArgs pa) {
    __shared__ unsigned sh[NB];
    __shared__ int s_l;
    for (int i = threadIdx.x; i < NB; i += blockDim.x) sh[i] = 0;
    if (threadIdx.x == 0) {
        int l = 0;
        while (blockIdx.x >= (unsigned)pa.cum[l + 1]) ++l;
        s_l = l;
    }
    __syncthreads();
    int l = s_l;
    int i = (blockIdx.x - pa.cum[l]) * 256 + threadIdx.x;
    if (i < pa.n[l]) {
        const int* row = pa.tab[l] + (size_t)i * 27;
        unsigned m = 0;
#pragma unroll
        for (int k = 0; k < 27; ++k) m |= (row[k] >= 0 ? 1u : 0u) << k;
        unsigned key = (m * 2654435761u) >> 22;   // 10 bits
        g_keys[l][i] = key;
        atomicAdd(&sh[key], 1u);
    }
    __syncthreads();
    for (int j = threadIdx.x; j < NB; j += blockDim.x)
        if (sh[j]) atomicAdd(&g_hist[l * NB + j], sh[j]);
}

// 1024-thread blocks; each block re-scans its layer's hist in smem (identical
// exclusive prefix as the old standalone scan), then scatters 1024 rows.
__global__ void scatter_scan_all_kernel(PermArgs pa) {
    __shared__ unsigned s[NB];
    __shared__ unsigned offs[NB];
    __shared__ unsigned bcnt[NB];
    __shared__ unsigned bbase[NB];
    __shared__ int s_l;
    if (threadIdx.x == 0) {
        int l = 0;
        while (blockIdx.x >= (unsigned)pa.cum2[l + 1]) ++l;
        s_l = l;
    }
    __syncthreads();
    int l = s_l;
    int t = threadIdx.x;   // 0..1023 == NB
    unsigned h = g_hist[l * NB + t];
    s[t] = h;
    bcnt[t] = 0;
    __syncthreads();
    for (int d = 1; d < NB; d <<= 1) {
        unsigned v = (t >= d) ? s[t - d] : 0;
        __syncthreads();
        s[t] += v;
        __syncthreads();
    }
    offs[t] = s[t] - h;   // exclusive prefix
    __syncthreads();

    int i = (blockIdx.x - pa.cum2[l]) * 1024 + t;
    unsigned key = 0, rank = 0;
    bool valid = (i < pa.n[l]);
    if (valid) { key = g_keys[l][i]; rank = atomicAdd(&bcnt[key], 1u); }
    __syncthreads();
    if (bcnt[t]) bbase[t] = atomicAdd(&g_cnt[l * NB + t], bcnt[t]);
    __syncthreads();
    if (valid) g_perm[l][offs[key] + bbase[key] + rank] = i;
}

// ---------------------------------------------------------------------------
// f32x2 helpers
// ---------------------------------------------------------------------------
__device__ __forceinline__ void ffma2(unsigned long long& d, unsigned long long a,
                                      unsigned long long b) {
    asm("fma.rn.f32x2 %0, %1, %2, %0;" : "+l"(d) : "l"(a), "l"(b));
}
__device__ __forceinline__ unsigned long long packf2(float x) {
    unsigned long long r;
    unsigned int u = __float_as_uint(x);
    asm("mov.b64 %0, {%1, %1};" : "=l"(r) : "r"(u));
    return r;
}
__device__ __forceinline__ float2 unpackf2(unsigned long long v) {
    float2 f;
    asm("mov.b64 {%0, %1}, %2;" : "=f"(f.x), "=f"(f.y) : "l"(v));
    return f;
}

// final layer: out[n,3] = y[n,3]*a + b (no relu), affine from stats
__global__ void out_kernel(const float* __restrict__ y, const float* __restrict__ stats,
                           const float* __restrict__ g, const float* __restrict__ b,
                           float* __restrict__ out, int N) {
    __shared__ float sa[3], sb[3];
    int c = threadIdx.x;
    if (c < 3) {
        float invN = 1.0f / (float)N;
        float mu = stats[c] * invN;
        float var = stats[64 + c] * invN - mu * mu;
        float a = g[c] * rsqrtf(var + 1e-3f);
        sa[c] = a;
        sb[c] = b[c] - mu * a;
    }
    __syncthreads();
    int total = N * 3;
    for (int i = blockIdx.x * blockDim.x + threadIdx.x; i < total;
         i += gridDim.x * blockDim.x) {
        int j = i % 3;
        out[i] = fmaf(y[i], sa[j], sb[j]);
    }
}

// ---------------------------------------------------------------------------
// gemm3: gather-GEMM over (optionally) mask-sorted rows.  (byte-identical R14)
// ---------------------------------------------------------------------------
template <int CI, int CO, int NT, int RPT, int MB, bool APPLY, bool DENSE>
__launch_bounds__(NT, MB)
__global__ void gemm3_kernel(const float* __restrict__ in,
                             const int* __restrict__ nbr,
                             const float* __restrict__ W,    // [27][CI][CO]
                             const int* __restrict__ perm,   // [N] or null
                             const float* __restrict__ pstat,// prev stats
                             const float* __restrict__ pg,   // prev gamma
                             const float* __restrict__ pb,   // prev beta
                             int prevN,
                             float* __restrict__ out,        // [N][CO] raw
                             float* __restrict__ stats,      // [sum, sumsq]
                             int N) {
    constexpr int G = CO / 8;
    constexpr int ROWG = NT / G;
    constexpr int TN = ROWG * RPT;
    constexpr int CIP = CI + 4;
    constexpr int WR = (32 / G) * RPT;   // rows owned by one warp
    constexpr int C4 = CI / 4;
    constexpr int H = CO / 2;

    extern __shared__ float s_x[];       // TN*CIP (+ 2*CI*CO weights if DENSE)
    float* s_w = s_x + TN * CIP;

    __shared__ int s_rows[TN];
    __shared__ int s_nbr[TN * 27];
    __shared__ float s_stats[2][CO];
    __shared__ float s_a[CI], s_b[CI];

    const int tid = threadIdx.x;
    const int lane = tid & 31;
    const int warp = tid >> 5;
    const int rowbase = blockIdx.x * TN;

    if (tid < CO) { s_stats[0][tid] = 0.f; s_stats[1][tid] = 0.f; }
    if (APPLY) {
        for (int c = tid; c < CI; c += NT) {
            float invN = 1.0f / (float)prevN;
            float mu = pstat[c] * invN;
            float var = pstat[64 + c] * invN - mu * mu;
            float a = pg[c] * rsqrtf(var + 1e-3f);
            s_a[c] = a;
            s_b[c] = pb[c] - mu * a;
        }
    }
    for (int i = tid; i < TN; i += NT) {
        int gr = rowbase + i;
        s_rows[i] = (gr < N) ? (perm ? perm[gr] : gr) : -1;
    }
    __syncthreads();
    for (int i = tid; i < TN * 27; i += NT) {
        int r = i / 27;
        int k = i - r * 27;
        int row = s_rows[r];
        s_nbr[i] = (row >= 0) ? nbr[(size_t)row * 27 + k] : -1;
    }
    __syncthreads();

    const int cg = tid % G;
    const int rg = tid / G;
    const int r0 = rg * RPT;
    const int wbase = warp * WR;

    unsigned m = 0;
    for (int i = lane; i < WR * 27; i += 32) {
        int r = wbase + i / 27;
        int k = i - (i / 27) * 27;
        if (s_nbr[r * 27 + k] >= 0) m |= 1u << k;
    }
    m = __reduce_or_sync(0xffffffffu, m);

    unsigned long long acc[RPT][4];
#pragma unroll
    for (int i = 0; i < RPT; ++i)
#pragma unroll
        for (int j = 0; j < 4; ++j) acc[i][j] = 0ULL;

    auto gather = [&](int k) {
        for (int i = lane; i < WR * C4; i += 32) {
            int rl = i / C4;
            int c4 = i - rl * C4;
            int r = wbase + rl;
            int idx = s_nbr[r * 27 + k];
            float4 val = make_float4(0.f, 0.f, 0.f, 0.f);
            if (idx >= 0) {
                val = *(const float4*)(in + (size_t)idx * CI + c4 * 4);
                if (APPLY) {
                    int c = c4 * 4;
                    val.x = fmaxf(fmaf(val.x, s_a[c + 0], s_b[c + 0]), 0.f);
                    val.y = fmaxf(fmaf(val.y, s_a[c + 1], s_b[c + 1]), 0.f);
                    val.z = fmaxf(fmaf(val.z, s_a[c + 2], s_b[c + 2]), 0.f);
                    val.w = fmaxf(fmaf(val.w, s_a[c + 3], s_b[c + 3]), 0.f);
                }
            }
            *(float4*)(s_x + r * CIP + c4 * 4) = val;
        }
    };

    auto compute = [&](const ulonglong2* __restrict__ Wk) {
#pragma unroll 2
        for (int c = 0; c < CI; c += 2) {
            ulonglong2 wa0 = Wk[(c * CO + 4 * cg) >> 2];
            ulonglong2 wa1 = Wk[(c * CO + H + 4 * cg) >> 2];
            ulonglong2 wb0 = Wk[((c + 1) * CO + 4 * cg) >> 2];
            ulonglong2 wb1 = Wk[((c + 1) * CO + H + 4 * cg) >> 2];
#pragma unroll
            for (int i = 0; i < RPT; ++i) {
                float2 xv = *(const float2*)(s_x + (r0 + i) * CIP + c);
                unsigned long long xa = packf2(xv.x);
                unsigned long long xb = packf2(xv.y);
                ffma2(acc[i][0], xa, wa0.x);
                ffma2(acc[i][1], xa, wa0.y);
                ffma2(acc[i][2], xa, wa1.x);
                ffma2(acc[i][3], xa, wa1.y);
                ffma2(acc[i][0], xb, wb0.x);
                ffma2(acc[i][1], xb, wb0.y);
                ffma2(acc[i][2], xb, wb1.x);
                ffma2(acc[i][3], xb, wb1.y);
            }
        }
    };

    if (DENSE) {
        {
            const float4* Wk4 = (const float4*)W;
            for (int v = tid; v < CI * CO / 4; v += NT)
                ((float4*)s_w)[v] = Wk4[v];
        }
        __syncthreads();
        for (int k = 0; k < 27; ++k) {
            if (k + 1 < 27) {
                const float4* Wn = (const float4*)(W + (size_t)(k + 1) * CI * CO);
                float4* dst = (float4*)(s_w + ((k + 1) & 1) * (CI * CO));
                for (int v = tid; v < CI * CO / 4; v += NT) dst[v] = Wn[v];
            }
            if ((m >> k) & 1u) {
                gather(k);
                __syncwarp();
                compute((const ulonglong2*)(s_w + (k & 1) * (CI * CO)));
            }
            __syncthreads();
        }
    } else {
        unsigned mm = m;
        while (mm) {
            const int k = __ffs(mm) - 1;
            mm &= mm - 1;
            gather(k);
            __syncwarp();
            compute((const ulonglong2*)(W + (size_t)k * CI * CO));
            __syncwarp();
        }
    }

#pragma unroll
    for (int j = 0; j < 4; ++j) {
        float s1 = 0.f, s2 = 0.f, t1 = 0.f, t2 = 0.f;
#pragma unroll
        for (int i = 0; i < RPT; ++i) {
            if (s_rows[r0 + i] >= 0) {
                float2 p = unpackf2(acc[i][j]);
                s1 += p.x; s2 += p.x * p.x;
                t1 += p.y; t2 += p.y * p.y;
            }
        }
        int base = (j < 2) ? (4 * cg + 2 * j) : (H + 4 * cg + 2 * (j - 2));
        atomicAdd(&s_stats[0][base + 0], s1);
        atomicAdd(&s_stats[1][base + 0], s2);
        atomicAdd(&s_stats[0][base + 1], t1);
        atomicAdd(&s_stats[1][base + 1], t2);
    }
#pragma unroll
    for (int i = 0; i < RPT; ++i) {
        int row = s_rows[r0 + i];
        if (row >= 0) {
            float2 p0 = unpackf2(acc[i][0]);
            float2 p1 = unpackf2(acc[i][1]);
            float2 p2 = unpackf2(acc[i][2]);
            float2 p3 = unpackf2(acc[i][3]);
            *(float4*)(out + (size_t)row * CO + 4 * cg) =
                make_float4(p0.x, p0.y, p1.x, p1.y);
            *(float4*)(out + (size_t)row * CO + H + 4 * cg) =
                make_float4(p2.x, p2.y, p3.x, p3.y);
        }
    }
    __syncthreads();
    if (tid < CO) {
        atomicAdd(&stats[tid], s_stats[0][tid]);
        atomicAdd(&stats[64 + tid], s_stats[1][tid]);
    }
}

// ---------------------------------------------------------------------------
// Final 16->3 conv  (byte-identical R14)
// ---------------------------------------------------------------------------
__launch_bounds__(256, 4)
__global__ void gemm_c5_kernel(const float* __restrict__ in,
                               const int* __restrict__ nbr,
                               const float* __restrict__ W,     // [27][16][3]
                               const int* __restrict__ perm,
                               const float* __restrict__ pstat,
                               const float* __restrict__ pg,
                               const float* __restrict__ pb,
                               int prevN,
                               float* __restrict__ out,
                               float* __restrict__ stats,
                               int N) {
    constexpr int CI = 16, TN = 256;

    __shared__ int s_rows[TN];
    __shared__ int s_nbr[TN * 27];
    __shared__ float s_a[CI], s_b[CI];
    __shared__ float s_stats[2][4];

    const int tid = threadIdx.x;
    const int rowbase = blockIdx.x * TN;

    if (tid < 4) { s_stats[0][tid] = 0.f; s_stats[1][tid] = 0.f; }
    if (tid < CI) {
        float invN = 1.0f / (float)prevN;
        float mu = pstat[tid] * invN;
        float var = pstat[64 + tid] * invN - mu * mu;
        float a = pg[tid] * rsqrtf(var + 1e-3f);
        s_a[tid] = a;
        s_b[tid] = pb[tid] - mu * a;
    }
    {
        int gr = rowbase + tid;
        s_rows[tid] = (gr < N) ? perm[gr] : -1;
    }
    __syncthreads();
    for (int i = tid; i < TN * 27; i += 256) {
        int r = i / 27;
        int row = s_rows[r];
        s_nbr[i] = (row >= 0) ? nbr[(size_t)row * 27 + (i - r * 27)] : -1;
    }
    __syncthreads();

    unsigned m = 0;
#pragma unroll
    for (int k = 0; k < 27; ++k)
        if (s_nbr[tid * 27 + k] >= 0) m |= 1u << k;
    unsigned wm = __reduce_or_sync(0xffffffffu, m);

    float acc[3] = {0.f, 0.f, 0.f};

    while (wm) {
        const int k = __ffs(wm) - 1;
        wm &= wm - 1;
        int idx = s_nbr[tid * 27 + k];
        if (idx >= 0) {
            const float* xr = in + (size_t)idx * CI;
            const float* wk = W + (size_t)k * CI * 3;
#pragma unroll
            for (int c4 = 0; c4 < 4; ++c4) {
                float4 v = *(const float4*)(xr + c4 * 4);
                int c = c4 * 4;
                v.x = fmaxf(fmaf(v.x, s_a[c + 0], s_b[c + 0]), 0.f);
                v.y = fmaxf(fmaf(v.y, s_a[c + 1], s_b[c + 1]), 0.f);
                v.z = fmaxf(fmaf(v.z, s_a[c + 2], s_b[c + 2]), 0.f);
                v.w = fmaxf(fmaf(v.w, s_a[c + 3], s_b[c + 3]), 0.f);
                float xs[4] = {v.x, v.y, v.z, v.w};
#pragma unroll
                for (int u = 0; u < 4; ++u) {
                    acc[0] = fmaf(xs[u], __ldg(wk + (c + u) * 3 + 0), acc[0]);
                    acc[1] = fmaf(xs[u], __ldg(wk + (c + u) * 3 + 1), acc[1]);
                    acc[2] = fmaf(xs[u], __ldg(wk + (c + u) * 3 + 2), acc[2]);
                }
            }
        }
    }

    int row = s_rows[tid];
#pragma unroll
    for (int j = 0; j < 3; ++j) {
        float y = (row >= 0) ? acc[j] : 0.f;
        atomicAdd(&s_stats[0][j], y);
        atomicAdd(&s_stats[1][j], y * y);
    }
    if (row >= 0) {
#pragma unroll
        for (int j = 0; j < 3; ++j) out[(size_t)row * 3 + j] = acc[j];
    }
    __syncthreads();
    if (tid < 3) {
        atomicAdd(&stats[tid], s_stats[0][tid]);
        atomicAdd(&stats[64 + tid], s_stats[1][tid]);
    }
}

extern "C" void kernel_launch(void* const* d_in, const int* in_sizes, int n_in,
                              void* d_out, int out_size) {
    const int* nbr4  = (const int*)d_in[0];
    const int* inv43 = (const int*)d_in[1];
    const int* nbr3  = (const int*)d_in[2];
    const int* inv32 = (const int*)d_in[3];
    const int* nbr2  = (const int*)d_in[4];
    const int* inv21 = (const int*)d_in[5];
    const int* nbr1  = (const int*)d_in[6];
    const float* x   = (const float*)d_in[7];

    const float* W_m4 = (const float*)d_in[8];
    const float* g_m4 = (const float*)d_in[9];
    const float* b_m4 = (const float*)d_in[10];
    const float* W_i4 = (const float*)d_in[11];
    const float* g_i4 = (const float*)d_in[12];
    const float* b_i4 = (const float*)d_in[13];
    const float* W_m3 = (const float*)d_in[14];
    const float* g_m3 = (const float*)d_in[15];
    const float* b_m3 = (const float*)d_in[16];
    const float* W_i3 = (const float*)d_in[17];
    const float* g_i3 = (const float*)d_in[18];
    const float* b_i3 = (const float*)d_in[19];
    const float* W_m2 = (const float*)d_in[20];
    const float* g_m2 = (const float*)d_in[21];
    const float* b_m2 = (const float*)d_in[22];
    const float* W_i2 = (const float*)d_in[23];
    const float* g_i2 = (const float*)d_in[24];
    const float* b_i2 = (const float*)d_in[25];
    const float* W_m1 = (const float*)d_in[26];
    const float* g_m1 = (const float*)d_in[27];
    const float* b_m1 = (const float*)d_in[28];
    const float* W_c5 = (const float*)d_in[29];
    const float* g_c5 = (const float*)d_in[30];
    const float* b_c5 = (const float*)d_in[31];

    const int n4 = in_sizes[0] / 27;
    const int n3 = in_sizes[1] / 27;
    const int n2 = in_sizes[3] / 27;
    const int n1 = in_sizes[5] / 27;

    float *bufA, *bufB, *stats;
    int* perm;
    unsigned *hist, *cnt;
    cudaGetSymbolAddress((void**)&bufA, g_bufA);
    cudaGetSymbolAddress((void**)&bufB, g_bufB);
    cudaGetSymbolAddress((void**)&stats, g_stats);
    cudaGetSymbolAddress((void**)&perm, g_perm);
    cudaGetSymbolAddress((void**)&hist, g_hist);
    cudaGetSymbolAddress((void**)&cnt, g_cnt);

    // dynamic smem: s_x = TN*(CI+4)*4; DENSE adds 2*CI*CO*4 for s_w
    constexpr int SM_DENSE64 = (128 * 68 + 2 * 64 * 64) * 4;  // 67584
    constexpr int SM_CI64 = 128 * 68 * 4;                      // 34816
    constexpr int SM_CI32 = 128 * 36 * 4;                      // 18432
    constexpr int SM_CI16 = 128 * 20 * 4;                      // 10240

    cudaFuncSetAttribute(gemm3_kernel<64, 64, 256, 4, 2, false, true>,
                         cudaFuncAttributeMaxDynamicSharedMemorySize, SM_DENSE64);
    cudaFuncSetAttribute(gemm3_kernel<64, 64, 256, 4, 2, true, false>,
                         cudaFuncAttributeMaxDynamicSharedMemorySize, SM_CI64);
    cudaFuncSetAttribute(gemm3_kernel<64, 32, 128, 4, 4, true, false>,
                         cudaFuncAttributeMaxDynamicSharedMemorySize, SM_CI64);
    cudaFuncSetAttribute(gemm3_kernel<32, 32, 128, 4, 4, true, false>,
                         cudaFuncAttributeMaxDynamicSharedMemorySize, SM_CI32);
    cudaFuncSetAttribute(gemm3_kernel<32, 16, 128, 2, 4, true, false>,
                         cudaFuncAttributeMaxDynamicSharedMemorySize, SM_CI32);
    cudaFuncSetAttribute(gemm3_kernel<16, 16, 128, 2, 4, true, false>,
                         cudaFuncAttributeMaxDynamicSharedMemorySize, SM_CI16);

    PermArgs pa;
    pa.tab[0] = nbr4;  pa.n[0] = n4;
    pa.tab[1] = inv43; pa.n[1] = n3;
    pa.tab[2] = nbr3;  pa.n[2] = n3;
    pa.tab[3] = inv32; pa.n[3] = n2;
    pa.tab[4] = nbr2;  pa.n[4] = n2;
    pa.tab[5] = inv21; pa.n[5] = n1;
    pa.tab[6] = nbr1;  pa.n[6] = n1;
    pa.cum[0] = 0;
    pa.cum2[0] = 0;
    for (int l = 0; l < 7; ++l) {
        pa.cum[l + 1] = pa.cum[l] + (pa.n[l] + 255) / 256;
        pa.cum2[l + 1] = pa.cum2[l] + (pa.n[l] + 1023) / 1024;
    }
    int nblk = pa.cum[7];
    int nblk2 = pa.cum2[7];

    // zeroing via memset nodes (not kernel launches -> keeps capture slots)
    cudaMemsetAsync(hist, 0, 7 * NB * sizeof(unsigned), 0);
    cudaMemsetAsync(cnt, 0, 7 * NB * sizeof(unsigned), 0);
    cudaMemsetAsync(stats, 0, 8 * 2 * 64 * sizeof(float), 0);

    mask_hist_all_kernel<<<nblk, 256>>>(pa);          // kernel #0
    scatter_scan_all_kernel<<<nblk2, 1024>>>(pa);     // kernel #1

    // L1: m4 (x -> A), 64->64, N=n4, DENSE, identity perm.   kernel #2
    gemm3_kernel<64, 64, 256, 4, 2, false, true><<<(n4 + 127) / 128, 256, SM_DENSE64>>>(
        x, nbr4, W_m4, nullptr, nullptr, nullptr, nullptr, 0,
        bufA, stats + 0 * 128, n4);

    // L2: i4 (A -> B), 64->64, N=n3.                          kernel #3 (ncu)
    gemm3_kernel<64, 64, 256, 4, 2, true, false><<<(n3 + 127) / 128, 256, SM_CI64>>>(
        bufA, inv43, W_i4, perm + 1 * MAXROWS,
        stats + 0 * 128, g_m4, b_m4, n4, bufB, stats + 1 * 128, n3);

    // L3: m3 (B -> A), 64->64, N=n3
    gemm3_kernel<64, 64, 256, 4, 2, true, false><<<(n3 + 127) / 128, 256, SM_CI64>>>(
        bufB, nbr3, W_m3, perm + 2 * MAXROWS,
        stats + 1 * 128, g_i4, b_i4, n3, bufA, stats + 2 * 128, n3);

    // L4: i3 (A -> B), 64->32, N=n2
    gemm3_kernel<64, 32, 128, 4, 4, true, false><<<(n2 + 127) / 128, 128, SM_CI64>>>(
        bufA, inv32, W_i3, perm + 3 * MAXROWS,
        stats + 2 * 128, g_m3, b_m3, n3, bufB, stats + 3 * 128, n2);

    // L5: m2 (B -> A), 32->32, N=n2
    gemm3_kernel<32, 32, 128, 4, 4, true, false><<<(n2 + 127) / 128, 128, SM_CI32>>>(
        bufB, nbr2, W_m2, perm + 4 * MAXROWS,
        stats + 3 * 128, g_i3, b_i3, n2, bufA, stats + 4 * 128, n2);

    // L6: i2 (A -> B), 32->16, N=n1
    gemm3_kernel<32, 16, 128, 2, 4, true, false><<<(n1 + 127) / 128, 128, SM_CI32>>>(
        bufA, inv21, W_i2, perm + 5 * MAXROWS,
        stats + 4 * 128, g_m2, b_m2, n2, bufB, stats + 5 * 128, n1);

    // L7: m1 (B -> A), 16->16, N=n1
    gemm3_kernel<16, 16, 128, 2, 4, true, false><<<(n1 + 127) / 128, 128, SM_CI16>>>(
        bufB, nbr1, W_m1, perm + 6 * MAXROWS,
        stats + 5 * 128, g_i2, b_i2, n1, bufA, stats + 6 * 128, n1);

    // L8: c5 (A -> B raw), 16->3
    gemm_c5_kernel<<<(n1 + 255) / 256, 256>>>(
        bufA, nbr1, W_c5, perm + 6 * MAXROWS,
        stats + 6 * 128, g_m1, b_m1, n1, bufB, stats + 7 * 128, n1);

    // final normalize (no relu)
    out_kernel<<<256, 256>>>(bufB, stats + 7 * 128, g_c5, b_c5,
                             (float*)d_out, n1);
}

// round 17
// speedup vs baseline: 1.5056x; 1.5056x over previous
#include <cuda_runtime.h>
#include <math.h>

// ---------------------------------------------------------------------------
// VoxelBackBone8x decoder: 8 x (gather-GEMM over 27 taps + BN + relu)
// R17: base = R14 (1244us best). ONE correctness-preserving transform:
//      sparse tap loop optionally 2-unrolled (U2) with two DISJOINT s_x
//      buffers -- gather(buf0,k0); gather(buf1,k1); syncwarp; compute(buf0);
//      compute(buf1); syncwarp. gather/compute bodies are byte-identical to
//      the passing R14 code (only a buffer base offset added). U2 on L2/L3.
// ---------------------------------------------------------------------------

#define MAXROWS 102400
#define NB 1024

__device__ float g_bufA[MAXROWS * 64];
__device__ float g_bufB[MAXROWS * 64];
__device__ float g_stats[8 * 2 * 64];   // per layer: [sum(64), sumsq(64)]
__device__ int      g_perm[7][MAXROWS];
__device__ unsigned g_keys[7][MAXROWS];
__device__ unsigned g_hist[7 * NB];
__device__ unsigned g_offs[7 * NB];
__device__ unsigned g_cnt[7 * NB];

struct PermArgs {
    const int* tab[7];
    int n[7];
    int cum[8];   // cumulative block counts (256-thread blocks)
};

// zeroes hist + cnt + stats in one launch
__global__ void zero_all_kernel() {
    int t = blockIdx.x * blockDim.x + threadIdx.x;
    if (t < 7 * NB) { g_hist[t] = 0u; g_cnt[t] = 0u; }
    if (t < 8 * 2 * 64) g_stats[t] = 0.f;
}

// ---------------------------------------------------------------------------
// Fused permutation build over all 7 layers.  (R14 pipeline, verbatim)
// ---------------------------------------------------------------------------
__global__ void mask_hist_all_kernel(PermArgs pa) {
    __shared__ unsigned sh[NB];
    __shared__ int s_l;
    for (int i = threadIdx.x; i < NB; i += blockDim.x) sh[i] = 0;
    if (threadIdx.x == 0) {
        int l = 0;
        while (blockIdx.x >= (unsigned)pa.cum[l + 1]) ++l;
        s_l = l;
    }
    __syncthreads();
    int l = s_l;
    int i = (blockIdx.x - pa.cum[l]) * 256 + threadIdx.x;
    if (i < pa.n[l]) {
        const int* row = pa.tab[l] + (size_t)i * 27;
        unsigned m = 0;
#pragma unroll
        for (int k = 0; k < 27; ++k) m |= (row[k] >= 0 ? 1u : 0u) << k;
        unsigned key = (m * 2654435761u) >> 22;   // 10 bits
        g_keys[l][i] = key;
        atomicAdd(&sh[key], 1u);
    }
    __syncthreads();
    for (int j = threadIdx.x; j < NB; j += blockDim.x)
        if (sh[j]) atomicAdd(&g_hist[l * NB + j], sh[j]);
}

__global__ void scan_all_kernel() {   // grid = 7, block = NB
    __shared__ unsigned s[NB];
    int l = blockIdx.x;
    int t = threadIdx.x;
    unsigned h = g_hist[l * NB + t];
    s[t] = h;
    __syncthreads();
    for (int d = 1; d < NB; d <<= 1) {
        unsigned v = (t >= d) ? s[t - d] : 0;
        __syncthreads();
        s[t] += v;
        __syncthreads();
    }
    g_offs[l * NB + t] = s[t] - h;   // exclusive prefix
}

__global__ void scatter_all_kernel(PermArgs pa) {
    __shared__ unsigned bcnt[NB];
    __shared__ unsigned bbase[NB];
    __shared__ int s_l;
    for (int i = threadIdx.x; i < NB; i += blockDim.x) bcnt[i] = 0;
    if (threadIdx.x == 0) {
        int l = 0;
        while (blockIdx.x >= (unsigned)pa.cum[l + 1]) ++l;
        s_l = l;
    }
    __syncthreads();
    int l = s_l;
    int i = (blockIdx.x - pa.cum[l]) * 256 + threadIdx.x;
    unsigned key = 0, rank = 0;
    bool valid = (i < pa.n[l]);
    if (valid) { key = g_keys[l][i]; rank = atomicAdd(&bcnt[key], 1u); }
    __syncthreads();
    for (int j = threadIdx.x; j < NB; j += blockDim.x)
        if (bcnt[j]) bbase[j] = atomicAdd(&g_cnt[l * NB + j], bcnt[j]);
    __syncthreads();
    if (valid) g_perm[l][g_offs[l * NB + key] + bbase[key] + rank] = i;
}

// ---------------------------------------------------------------------------
// f32x2 helpers
// ---------------------------------------------------------------------------
__device__ __forceinline__ void ffma2(unsigned long long& d, unsigned long long a,
                                      unsigned long long b) {
    asm("fma.rn.f32x2 %0, %1, %2, %0;" : "+l"(d) : "l"(a), "l"(b));
}
__device__ __forceinline__ unsigned long long packf2(float x) {
    unsigned long long r;
    unsigned int u = __float_as_uint(x);
    asm("mov.b64 %0, {%1, %1};" : "=l"(r) : "r"(u));
    return r;
}
__device__ __forceinline__ float2 unpackf2(unsigned long long v) {
    float2 f;
    asm("mov.b64 {%0, %1}, %2;" : "=f"(f.x), "=f"(f.y) : "l"(v));
    return f;
}

// final layer: out[n,3] = y[n,3]*a + b (no relu), affine from stats
__global__ void out_kernel(const float* __restrict__ y, const float* __restrict__ stats,
                           const float* __restrict__ g, const float* __restrict__ b,
                           float* __restrict__ out, int N) {
    __shared__ float sa[3], sb[3];
    int c = threadIdx.x;
    if (c < 3) {
        float invN = 1.0f / (float)N;
        float mu = stats[c] * invN;
        float var = stats[64 + c] * invN - mu * mu;
        float a = g[c] * rsqrtf(var + 1e-3f);
        sa[c] = a;
        sb[c] = b[c] - mu * a;
    }
    __syncthreads();
    int total = N * 3;
    for (int i = blockIdx.x * blockDim.x + threadIdx.x; i < total;
         i += gridDim.x * blockDim.x) {
        int j = i % 3;
        out[i] = fmaf(y[i], sa[j], sb[j]);
    }
}

// ---------------------------------------------------------------------------
// gemm3: gather-GEMM over (optionally) mask-sorted rows.
//   DENSE: block-synchronous tap loop with double-buffered smem weights (L1).
//  !DENSE: warp-private tap loop; U2=true adds 2-tap unroll over two disjoint
//          s_x buffers (gather/compute bodies unchanged from the passing
//          single-buffer version; only a base offset differs).
// ---------------------------------------------------------------------------
template <int CI, int CO, int NT, int RPT, int MB, bool APPLY, bool DENSE, bool U2>
__launch_bounds__(NT, MB)
__global__ void gemm3_kernel(const float* __restrict__ in,
                             const int* __restrict__ nbr,
                             const float* __restrict__ W,    // [27][CI][CO]
                             const int* __restrict__ perm,   // [N] or null
                             const float* __restrict__ pstat,
                             const float* __restrict__ pg,
                             const float* __restrict__ pb,
                             int prevN,
                             float* __restrict__ out,
                             float* __restrict__ stats,
                             int N) {
    constexpr int G = CO / 8;
    constexpr int ROWG = NT / G;
    constexpr int TN = ROWG * RPT;
    constexpr int CIP = CI + 4;
    constexpr int WR = (32 / G) * RPT;
    constexpr int C4 = CI / 4;
    constexpr int H = CO / 2;
    constexpr int XBUF = TN * CIP;       // one s_x buffer, floats

    extern __shared__ float s_x[];       // XBUF (x2 if U2); DENSE: + 2*CI*CO
    float* s_w = s_x + XBUF;             // (DENSE only; DENSE implies !U2)

    __shared__ int s_rows[TN];
    __shared__ int s_nbr[TN * 27];
    __shared__ float s_stats[2][CO];
    __shared__ float s_a[CI], s_b[CI];

    const int tid = threadIdx.x;
    const int lane = tid & 31;
    const int warp = tid >> 5;
    const int rowbase = blockIdx.x * TN;

    if (tid < CO) { s_stats[0][tid] = 0.f; s_stats[1][tid] = 0.f; }
    if (APPLY) {
        for (int c = tid; c < CI; c += NT) {
            float invN = 1.0f / (float)prevN;
            float mu = pstat[c] * invN;
            float var = pstat[64 + c] * invN - mu * mu;
            float a = pg[c] * rsqrtf(var + 1e-3f);
            s_a[c] = a;
            s_b[c] = pb[c] - mu * a;
        }
    }
    for (int i = tid; i < TN; i += NT) {
        int gr = rowbase + i;
        s_rows[i] = (gr < N) ? (perm ? perm[gr] : gr) : -1;
    }
    __syncthreads();
    for (int i = tid; i < TN * 27; i += NT) {
        int r = i / 27;
        int k = i - r * 27;
        int row = s_rows[r];
        s_nbr[i] = (row >= 0) ? nbr[(size_t)row * 27 + k] : -1;
    }
    __syncthreads();

    const int cg = tid % G;
    const int rg = tid / G;
    const int r0 = rg * RPT;
    const int wbase = warp * WR;

    unsigned m = 0;
    for (int i = lane; i < WR * 27; i += 32) {
        int r = wbase + i / 27;
        int k = i - (i / 27) * 27;
        if (s_nbr[r * 27 + k] >= 0) m |= 1u << k;
    }
    m = __reduce_or_sync(0xffffffffu, m);

    unsigned long long acc[RPT][4];
#pragma unroll
    for (int i = 0; i < RPT; ++i)
#pragma unroll
        for (int j = 0; j < 4; ++j) acc[i][j] = 0ULL;

    // gather into buffer `buf` for tap k — body identical to passing R14 code
    auto gather = [&](int buf, int k) {
        float* sx = s_x + buf * XBUF;
        for (int i = lane; i < WR * C4; i += 32) {
            int rl = i / C4;
            int c4 = i - rl * C4;
            int r = wbase + rl;
            int idx = s_nbr[r * 27 + k];
            float4 val = make_float4(0.f, 0.f, 0.f, 0.f);
            if (idx >= 0) {
                val = *(const float4*)(in + (size_t)idx * CI + c4 * 4);
                if (APPLY) {
                    int c = c4 * 4;
                    val.x = fmaxf(fmaf(val.x, s_a[c + 0], s_b[c + 0]), 0.f);
                    val.y = fmaxf(fmaf(val.y, s_a[c + 1], s_b[c + 1]), 0.f);
                    val.z = fmaxf(fmaf(val.z, s_a[c + 2], s_b[c + 2]), 0.f);
                    val.w = fmaxf(fmaf(val.w, s_a[c + 3], s_b[c + 3]), 0.f);
                }
            }
            *(float4*)(sx + r * CIP + c4 * 4) = val;
        }
    };

    auto compute = [&](int buf, const ulonglong2* __restrict__ Wk) {
        const float* sx = s_x + buf * XBUF;
#pragma unroll 2
        for (int c = 0; c < CI; c += 2) {
            ulonglong2 wa0 = Wk[(c * CO + 4 * cg) >> 2];
            ulonglong2 wa1 = Wk[(c * CO + H + 4 * cg) >> 2];
            ulonglong2 wb0 = Wk[((c + 1) * CO + 4 * cg) >> 2];
            ulonglong2 wb1 = Wk[((c + 1) * CO + H + 4 * cg) >> 2];
#pragma unroll
            for (int i = 0; i < RPT; ++i) {
                float2 xv = *(const float2*)(sx + (r0 + i) * CIP + c);
                unsigned long long xa = packf2(xv.x);
                unsigned long long xb = packf2(xv.y);
                ffma2(acc[i][0], xa, wa0.x);
                ffma2(acc[i][1], xa, wa0.y);
                ffma2(acc[i][2], xa, wa1.x);
                ffma2(acc[i][3], xa, wa1.y);
                ffma2(acc[i][0], xb, wb0.x);
                ffma2(acc[i][1], xb, wb0.y);
                ffma2(acc[i][2], xb, wb1.x);
                ffma2(acc[i][3], xb, wb1.y);
            }
        }
    };

    if (DENSE) {
        {
            const float4* Wk4 = (const float4*)W;
            for (int v = tid; v < CI * CO / 4; v += NT)
                ((float4*)s_w)[v] = Wk4[v];
        }
        __syncthreads();
        for (int k = 0; k < 27; ++k) {
            if (k + 1 < 27) {
                const float4* Wn = (const float4*)(W + (size_t)(k + 1) * CI * CO);
                float4* dst = (float4*)(s_w + ((k + 1) & 1) * (CI * CO));
                for (int v = tid; v < CI * CO / 4; v += NT) dst[v] = Wn[v];
            }
            if ((m >> k) & 1u) {
                gather(0, k);
                __syncwarp();
                compute(0, (const ulonglong2*)(s_w + (k & 1) * (CI * CO)));
            }
            __syncthreads();
        }
    } else if (U2) {
        // 2-unrolled warp-private loop over disjoint buffers
        unsigned mm = m;
        while (mm) {
            int k0 = __ffs(mm) - 1;
            mm &= mm - 1;
            int k1 = -1;
            if (mm) { k1 = __ffs(mm) - 1; mm &= mm - 1; }
            gather(0, k0);
            if (k1 >= 0) gather(1, k1);
            __syncwarp();
            compute(0, (const ulonglong2*)(W + (size_t)k0 * CI * CO));
            if (k1 >= 0)
                compute(1, (const ulonglong2*)(W + (size_t)k1 * CI * CO));
            __syncwarp();
        }
    } else {
        unsigned mm = m;
        while (mm) {
            const int k = __ffs(mm) - 1;
            mm &= mm - 1;
            gather(0, k);
            __syncwarp();
            compute(0, (const ulonglong2*)(W + (size_t)k * CI * CO));
            __syncwarp();
        }
    }

#pragma unroll
    for (int j = 0; j < 4; ++j) {
        float s1 = 0.f, s2 = 0.f, t1 = 0.f, t2 = 0.f;
#pragma unroll
        for (int i = 0; i < RPT; ++i) {
            if (s_rows[r0 + i] >= 0) {
                float2 p = unpackf2(acc[i][j]);
                s1 += p.x; s2 += p.x * p.x;
                t1 += p.y; t2 += p.y * p.y;
            }
        }
        int base = (j < 2) ? (4 * cg + 2 * j) : (H + 4 * cg + 2 * (j - 2));
        atomicAdd(&s_stats[0][base + 0], s1);
        atomicAdd(&s_stats[1][base + 0], s2);
        atomicAdd(&s_stats[0][base + 1], t1);
        atomicAdd(&s_stats[1][base + 1], t2);
    }
#pragma unroll
    for (int i = 0; i < RPT; ++i) {
        int row = s_rows[r0 + i];
        if (row >= 0) {
            float2 p0 = unpackf2(acc[i][0]);
            float2 p1 = unpackf2(acc[i][1]);
            float2 p2 = unpackf2(acc[i][2]);
            float2 p3 = unpackf2(acc[i][3]);
            *(float4*)(out + (size_t)row * CO + 4 * cg) =
                make_float4(p0.x, p0.y, p1.x, p1.y);
            *(float4*)(out + (size_t)row * CO + H + 4 * cg) =
                make_float4(p2.x, p2.y, p3.x, p3.y);
        }
    }
    __syncthreads();
    if (tid < CO) {
        atomicAdd(&stats[tid], s_stats[0][tid]);
        atomicAdd(&stats[64 + tid], s_stats[1][tid]);
    }
}

// ---------------------------------------------------------------------------
// Final 16->3 conv  (R14 verbatim)
// ---------------------------------------------------------------------------
__launch_bounds__(256, 4)
__global__ void gemm_c5_kernel(const float* __restrict__ in,
                               const int* __restrict__ nbr,
                               const float* __restrict__ W,     // [27][16][3]
                               const int* __restrict__ perm,
                               const float* __restrict__ pstat,
                               const float* __restrict__ pg,
                               const float* __restrict__ pb,
                               int prevN,
                               float* __restrict__ out,
                               float* __restrict__ stats,
                               int N) {
    constexpr int CI = 16, TN = 256;

    __shared__ int s_rows[TN];
    __shared__ int s_nbr[TN * 27];
    __shared__ float s_a[CI], s_b[CI];
    __shared__ float s_stats[2][4];

    const int tid = threadIdx.x;
    const int rowbase = blockIdx.x * TN;

    if (tid < 4) { s_stats[0][tid] = 0.f; s_stats[1][tid] = 0.f; }
    if (tid < CI) {
        float invN = 1.0f / (float)prevN;
        float mu = pstat[tid] * invN;
        float var = pstat[64 + tid] * invN - mu * mu;
        float a = pg[tid] * rsqrtf(var + 1e-3f);
        s_a[tid] = a;
        s_b[tid] = pb[tid] - mu * a;
    }
    {
        int gr = rowbase + tid;
        s_rows[tid] = (gr < N) ? perm[gr] : -1;
    }
    __syncthreads();
    for (int i = tid; i < TN * 27; i += 256) {
        int r = i / 27;
        int row = s_rows[r];
        s_nbr[i] = (row >= 0) ? nbr[(size_t)row * 27 + (i - r * 27)] : -1;
    }
    __syncthreads();

    unsigned m = 0;
#pragma unroll
    for (int k = 0; k < 27; ++k)
        if (s_nbr[tid * 27 + k] >= 0) m |= 1u << k;
    unsigned wm = __reduce_or_sync(0xffffffffu, m);

    float acc[3] = {0.f, 0.f, 0.f};

    while (wm) {
        const int k = __ffs(wm) - 1;
        wm &= wm - 1;
        int idx = s_nbr[tid * 27 + k];
        if (idx >= 0) {
            const float* xr = in + (size_t)idx * CI;
            const float* wk = W + (size_t)k * CI * 3;
#pragma unroll
            for (int c4 = 0; c4 < 4; ++c4) {
                float4 v = *(const float4*)(xr + c4 * 4);
                int c = c4 * 4;
                v.x = fmaxf(fmaf(v.x, s_a[c + 0], s_b[c + 0]), 0.f);
                v.y = fmaxf(fmaf(v.y, s_a[c + 1], s_b[c + 1]), 0.f);
                v.z = fmaxf(fmaf(v.z, s_a[c + 2], s_b[c + 2]), 0.f);
                v.w = fmaxf(fmaf(v.w, s_a[c + 3], s_b[c + 3]), 0.f);
                float xs[4] = {v.x, v.y, v.z, v.w};
#pragma unroll
                for (int u = 0; u < 4; ++u) {
                    acc[0] = fmaf(xs[u], __ldg(wk + (c + u) * 3 + 0), acc[0]);
                    acc[1] = fmaf(xs[u], __ldg(wk + (c + u) * 3 + 1), acc[1]);
                    acc[2] = fmaf(xs[u], __ldg(wk + (c + u) * 3 + 2), acc[2]);
                }
            }
        }
    }

    int row = s_rows[tid];
#pragma unroll
    for (int j = 0; j < 3; ++j) {
        float y = (row >= 0) ? acc[j] : 0.f;
        atomicAdd(&s_stats[0][j], y);
        atomicAdd(&s_stats[1][j], y * y);
    }
    if (row >= 0) {
#pragma unroll
        for (int j = 0; j < 3; ++j) out[(size_t)row * 3 + j] = acc[j];
    }
    __syncthreads();
    if (tid < 3) {
        atomicAdd(&stats[tid], s_stats[0][tid]);
        atomicAdd(&stats[64 + tid], s_stats[1][tid]);
    }
}

extern "C" void kernel_launch(void* const* d_in, const int* in_sizes, int n_in,
                              void* d_out, int out_size) {
    const int* nbr4  = (const int*)d_in[0];
    const int* inv43 = (const int*)d_in[1];
    const int* nbr3  = (const int*)d_in[2];
    const int* inv32 = (const int*)d_in[3];
    const int* nbr2  = (const int*)d_in[4];
    const int* inv21 = (const int*)d_in[5];
    const int* nbr1  = (const int*)d_in[6];
    const float* x   = (const float*)d_in[7];

    const float* W_m4 = (const float*)d_in[8];
    const float* g_m4 = (const float*)d_in[9];
    const float* b_m4 = (const float*)d_in[10];
    const float* W_i4 = (const float*)d_in[11];
    const float* g_i4 = (const float*)d_in[12];
    const float* b_i4 = (const float*)d_in[13];
    const float* W_m3 = (const float*)d_in[14];
    const float* g_m3 = (const float*)d_in[15];
    const float* b_m3 = (const float*)d_in[16];
    const float* W_i3 = (const float*)d_in[17];
    const float* g_i3 = (const float*)d_in[18];
    const float* b_i3 = (const float*)d_in[19];
    const float* W_m2 = (const float*)d_in[20];
    const float* g_m2 = (const float*)d_in[21];
    const float* b_m2 = (const float*)d_in[22];
    const float* W_i2 = (const float*)d_in[23];
    const float* g_i2 = (const float*)d_in[24];
    const float* b_i2 = (const float*)d_in[25];
    const float* W_m1 = (const float*)d_in[26];
    const float* g_m1 = (const float*)d_in[27];
    const float* b_m1 = (const float*)d_in[28];
    const float* W_c5 = (const float*)d_in[29];
    const float* g_c5 = (const float*)d_in[30];
    const float* b_c5 = (const float*)d_in[31];

    const int n4 = in_sizes[0] / 27;
    const int n3 = in_sizes[1] / 27;
    const int n2 = in_sizes[3] / 27;
    const int n1 = in_sizes[5] / 27;

    float *bufA, *bufB, *stats;
    int* perm;
    cudaGetSymbolAddress((void**)&bufA, g_bufA);
    cudaGetSymbolAddress((void**)&bufB, g_bufB);
    cudaGetSymbolAddress((void**)&stats, g_stats);
    cudaGetSymbolAddress((void**)&perm, g_perm);

    // dynamic smem: s_x = TN*(CI+4)*4 (x2 if U2); DENSE adds 2*CI*CO*4
    constexpr int SM_DENSE64 = (128 * 68 + 2 * 64 * 64) * 4;  // 67584
    constexpr int SM_U2C64 = 2 * 128 * 68 * 4;                 // 69632
    constexpr int SM_CI64 = 128 * 68 * 4;                      // 34816
    constexpr int SM_CI32 = 128 * 36 * 4;                      // 18432
    constexpr int SM_CI16 = 128 * 20 * 4;                      // 10240

    cudaFuncSetAttribute(gemm3_kernel<64, 64, 256, 4, 2, false, true, false>,
                         cudaFuncAttributeMaxDynamicSharedMemorySize, SM_DENSE64);
    cudaFuncSetAttribute(gemm3_kernel<64, 64, 256, 4, 2, true, false, true>,
                         cudaFuncAttributeMaxDynamicSharedMemorySize, SM_U2C64);
    cudaFuncSetAttribute(gemm3_kernel<64, 32, 128, 4, 4, true, false, false>,
                         cudaFuncAttributeMaxDynamicSharedMemorySize, SM_CI64);
    cudaFuncSetAttribute(gemm3_kernel<32, 32, 128, 4, 4, true, false, false>,
                         cudaFuncAttributeMaxDynamicSharedMemorySize, SM_CI32);
    cudaFuncSetAttribute(gemm3_kernel<32, 16, 128, 2, 4, true, false, false>,
                         cudaFuncAttributeMaxDynamicSharedMemorySize, SM_CI32);
    cudaFuncSetAttribute(gemm3_kernel<16, 16, 128, 2, 4, true, false, false>,
                         cudaFuncAttributeMaxDynamicSharedMemorySize, SM_CI16);

    // ---- perm build (R14 pipeline) ----
    PermArgs pa;
    pa.tab[0] = nbr4;  pa.n[0] = n4;
    pa.tab[1] = inv43; pa.n[1] = n3;
    pa.tab[2] = nbr3;  pa.n[2] = n3;
    pa.tab[3] = inv32; pa.n[3] = n2;
    pa.tab[4] = nbr2;  pa.n[4] = n2;
    pa.tab[5] = inv21; pa.n[5] = n1;
    pa.tab[6] = nbr1;  pa.n[6] = n1;
    pa.cum[0] = 0;
    for (int l = 0; l < 7; ++l)
        pa.cum[l + 1] = pa.cum[l] + (pa.n[l] + 255) / 256;
    int nblk = pa.cum[7];

    zero_all_kernel<<<(7 * NB + 255) / 256, 256>>>();   // #0
    mask_hist_all_kernel<<<nblk, 256>>>(pa);             // #1
    scan_all_kernel<<<7, NB>>>();                        // #2

    // L1: m4 (x -> A), 64->64, N=n4, DENSE, identity perm.   launch #3
    gemm3_kernel<64, 64, 256, 4, 2, false, true, false>
        <<<(n4 + 127) / 128, 256, SM_DENSE64>>>(
        x, nbr4, W_m4, nullptr, nullptr, nullptr, nullptr, 0,
        bufA, stats + 0 * 128, n4);

    scatter_all_kernel<<<nblk, 256>>>(pa);               // #4

    // L2: i4 (A -> B), 64->64, N=n3  (U2 sparse)
    gemm3_kernel<64, 64, 256, 4, 2, true, false, true>
        <<<(n3 + 127) / 128, 256, SM_U2C64>>>(
        bufA, inv43, W_i4, perm + 1 * MAXROWS,
        stats + 0 * 128, g_m4, b_m4, n4, bufB, stats + 1 * 128, n3);

    // L3: m3 (B -> A), 64->64, N=n3  (U2 sparse)
    gemm3_kernel<64, 64, 256, 4, 2, true, false, true>
        <<<(n3 + 127) / 128, 256, SM_U2C64>>>(
        bufB, nbr3, W_m3, perm + 2 * MAXROWS,
        stats + 1 * 128, g_i4, b_i4, n3, bufA, stats + 2 * 128, n3);

    // L4: i3 (A -> B), 64->32, N=n2
    gemm3_kernel<64, 32, 128, 4, 4, true, false, false>
        <<<(n2 + 127) / 128, 128, SM_CI64>>>(
        bufA, inv32, W_i3, perm + 3 * MAXROWS,
        stats + 2 * 128, g_m3, b_m3, n3, bufB, stats + 3 * 128, n2);

    // L5: m2 (B -> A), 32->32, N=n2
    gemm3_kernel<32, 32, 128, 4, 4, true, false, false>
        <<<(n2 + 127) / 128, 128, SM_CI32>>>(
        bufB, nbr2, W_m2, perm + 4 * MAXROWS,
        stats + 3 * 128, g_i3, b_i3, n2, bufA, stats + 4 * 128, n2);

    // L6: i2 (A -> B), 32->16, N=n1
    gemm3_kernel<32, 16, 128, 2, 4, true, false, false>
        <<<(n1 + 127) / 128, 128, SM_CI32>>>(
        bufA, inv21, W_i2, perm + 5 * MAXROWS,
        stats + 4 * 128, g_m2, b_m2, n2, bufB, stats + 5 * 128, n1);

    // L7: m1 (B -> A), 16->16, N=n1
    gemm3_kernel<16, 16, 128, 2, 4, true, false, false>
        <<<(n1 + 127) / 128, 128, SM_CI16>>>(
        bufB, nbr1, W_m1, perm + 6 * MAXROWS,
        stats + 5 * 128, g_i2, b_i2, n1, bufA, stats + 6 * 128, n1);

    // L8: c5 (A -> B raw), 16->3
    gemm_c5_kernel<<<(n1 + 255) / 256, 256>>>(
        bufA, nbr1, W_c5, perm + 6 * MAXROWS,
        stats + 6 * 128, g_m1, b_m1, n1, bufB, stats + 7 * 128, n1);

    // final normalize (no relu)
    out_kernel<<<256, 256>>>(bufB, stats + 7 * 128, g_c5, b_c5,
                             (float*)d_out, n1);
}